// round 10
// baseline (speedup 1.0000x reference)
#include <cuda_runtime.h>
#include <cuda_bf16.h>
#include <cstdint>

// Problem dims (fixed)
#define HID   1024
#define NBAT  16
#define SEQ   1024
#define MTOT  (NBAT * SEQ)        // 16384

// ============================================================================
// PTX helpers available on base sm_103 target
// ============================================================================
__device__ __forceinline__ uint32_t smem_u32_of(const void* p) {
    uint32_t a;
    asm("{ .reg .u64 t; cvta.to.shared.u64 t, %1; cvt.u32.u64 %0, t; }"
        : "=r"(a) : "l"(p));
    return a;
}

__device__ __forceinline__ void cp16(uint32_t s, const void* g) {
    asm volatile("cp.async.cg.shared.global [%0], [%1], 16;" :: "r"(s), "l"(g));
}
#define CP_COMMIT() asm volatile("cp.async.commit_group;" ::: "memory")
#define CP_WAIT(N)  asm volatile("cp.async.wait_group %0;" :: "n"(N) : "memory")

__device__ __forceinline__ void ldsm4(uint32_t* r, uint32_t addr) {
    asm volatile("ldmatrix.sync.aligned.m8n8.x4.shared.b16 {%0,%1,%2,%3}, [%4];"
        : "=r"(r[0]), "=r"(r[1]), "=r"(r[2]), "=r"(r[3]) : "r"(addr));
}

__device__ __forceinline__ void mma_bf16(float* c, const uint32_t* a, const uint32_t* b) {
    asm volatile(
        "mma.sync.aligned.m16n8k16.row.col.f32.bf16.bf16.f32 "
        "{%0,%1,%2,%3}, {%4,%5,%6,%7}, {%8,%9}, {%0,%1,%2,%3};"
        : "+f"(c[0]), "+f"(c[1]), "+f"(c[2]), "+f"(c[3])
        : "r"(a[0]), "r"(a[1]), "r"(a[2]), "r"(a[3]), "r"(b[0]), "r"(b[1]));
}

// Conflict-free swizzle for 64-byte smem rows (validated in R8):
__device__ __forceinline__ uint32_t sw64(uint32_t o) { return o ^ ((o >> 3) & 0x30); }

// ============================================================================
// Device global scratch (bf16 hi/lo intermediates; per-input buffers so all
// splits can be hoisted before the first GEMM)
// ============================================================================
__device__ __align__(16) __nv_bfloat16 g_Xmh[MTOT * HID], g_Xml[MTOT * HID];
__device__ __align__(16) __nv_bfloat16 g_Xth[MTOT * HID], g_Xtl[MTOT * HID];
__device__ __align__(16) __nv_bfloat16 g_Xeh[MTOT * HID], g_Xel[MTOT * HID];
__device__ __align__(16) __nv_bfloat16 g_Wqh[HID * HID],  g_Wql[HID * HID];
__device__ __align__(16) __nv_bfloat16 g_Wkh[HID * HID],  g_Wkl[HID * HID];
__device__ __align__(16) __nv_bfloat16 g_Wvh[HID * HID],  g_Wvl[HID * HID];
__device__ __align__(16) __nv_bfloat16 g_Qh[MTOT * HID],  g_Ql[MTOT * HID];
__device__ __align__(16) __nv_bfloat16 g_Kh[MTOT * HID],  g_Kl[MTOT * HID];
__device__ __align__(16) __nv_bfloat16 g_VTh[MTOT * HID], g_VTl[MTOT * HID]; // ld=16384
__device__ __align__(16) float         g_S [MTOT * SEQ];
__device__ __align__(16) __nv_bfloat16 g_Ph[MTOT * SEQ],  g_Pl[MTOT * SEQ];

// ============================================================================
// fp32 -> (bf16 hi, bf16 lo) elementwise split
// ============================================================================
__global__ void __launch_bounds__(256)
f32_to_split(const float* __restrict__ x, __nv_bfloat16* __restrict__ h,
             __nv_bfloat16* __restrict__ l, int n4)
{
    int i = blockIdx.x * blockDim.x + threadIdx.x;
    if (i >= n4) return;
    float4 v = reinterpret_cast<const float4*>(x)[i];
    __nv_bfloat16 h0 = __float2bfloat16(v.x);
    __nv_bfloat16 h1 = __float2bfloat16(v.y);
    __nv_bfloat16 h2 = __float2bfloat16(v.z);
    __nv_bfloat16 h3 = __float2bfloat16(v.w);
    __nv_bfloat16 l0 = __float2bfloat16(v.x - __bfloat162float(h0));
    __nv_bfloat16 l1 = __float2bfloat16(v.y - __bfloat162float(h1));
    __nv_bfloat16 l2 = __float2bfloat16(v.z - __bfloat162float(h2));
    __nv_bfloat16 l3 = __float2bfloat16(v.w - __bfloat162float(h3));
    reinterpret_cast<__nv_bfloat162*>(h)[2 * i + 0] = __halves2bfloat162(h0, h1);
    reinterpret_cast<__nv_bfloat162*>(h)[2 * i + 1] = __halves2bfloat162(h2, h3);
    reinterpret_cast<__nv_bfloat162*>(l)[2 * i + 0] = __halves2bfloat162(l0, l1);
    reinterpret_cast<__nv_bfloat162*>(l)[2 * i + 1] = __halves2bfloat162(l2, l3);
}

// ============================================================================
// Split-bf16 NT GEMM on mma.sync (HMMA), CTA tile 128x256:
//   D[m][n] = sum_k A[m][k]*B[n][k]  (hi*hi + hi*lo + lo*hi, fp32 accum)
//   K=1024, BK=32 (64B rows, sw64), 3-stage cp.async, 1 CTA/SM.
//   8 warps as 2(M) x 4(N); warp tile 64x64; MMA:LDSM ratio 6:1.
//   BIAS_MODE: 0 none, 1 per-col bias[n], 2 per-row bias[m]
//   OUT_SPLIT: 0 -> fp32 Cf;  1 -> bf16 pair (Ch, Cl)
// ============================================================================
#define KDEPTH   1024
#define BKC      32
#define NCHUNK   (KDEPTH / BKC)     // 32
#define ROWB     64                 // bytes per smem row
#define TILEA_B  8192               // 128 rows x 64 B
#define TILEB_B  16384              // 256 rows x 64 B
#define STAGE_B  (2 * TILEA_B + 2 * TILEB_B)   // 48 KB
#define NSTAGE   3
#define GEMM_SMEM (1024 + NSTAGE * STAGE_B)    // ~145 KB

template<int BIAS_MODE, int OUT_SPLIT>
__global__ void __launch_bounds__(256, 1)
gemm_split(const __nv_bfloat16* __restrict__ Ah, const __nv_bfloat16* __restrict__ Al,
           int lda, size_t sA,
           const __nv_bfloat16* __restrict__ Bh, const __nv_bfloat16* __restrict__ Bl,
           int ldb, size_t sB,
           const float* __restrict__ bias,
           float* __restrict__ Cf, __nv_bfloat16* __restrict__ Ch,
           __nv_bfloat16* __restrict__ Cl,
           int ldc, size_t sC)
{
    extern __shared__ char smem[];
    const int tid  = threadIdx.x;
    const int wid  = tid >> 5;
    const int lane = tid & 31;
    const int wm   = wid >> 2;     // 0..1  (M, 64 rows each)
    const int wn   = wid & 3;      // 0..3  (N, 64 cols each)
    const int z    = blockIdx.z;

    Ah += (size_t)z * sA;  Al += (size_t)z * sA;
    Bh += (size_t)z * sB;  Bl += (size_t)z * sB;
    if (OUT_SPLIT) { Ch += (size_t)z * sC; Cl += (size_t)z * sC; }
    else           { Cf += (size_t)z * sC; }

    const int rowBase = blockIdx.y * 128;
    const int colBase = blockIdx.x * 256;

    const uint32_t raw  = smem_u32_of(smem);
    const uint32_t base = (raw + 1023u) & ~1023u;

    const __nv_bfloat16* aAh = Ah + (size_t)rowBase * lda;
    const __nv_bfloat16* aAl = Al + (size_t)rowBase * lda;
    const __nv_bfloat16* aBh = Bh + (size_t)colBase * ldb;
    const __nv_bfloat16* aBl = Bl + (size_t)colBase * ldb;

    // ---- async chunk loader: A 128r + B 256r, 64B rows, sw64 ----
    auto load_chunk = [&](int k0, uint32_t stg) {
        const uint32_t sAh = stg;
        const uint32_t sAl = stg + TILEA_B;
        const uint32_t sBh = stg + 2 * TILEA_B;
        const uint32_t sBl = stg + 2 * TILEA_B + TILEB_B;
#pragma unroll
        for (int it = 0; it < 2; ++it) {             // A: 128 rows x 4 segs
            const int slot = tid + it * 256;         // 0..511
            const int r    = slot >> 2;
            const int seg  = slot & 3;
            const uint32_t so = sw64((uint32_t)(r * ROWB + seg * 16));
            const size_t ga = (size_t)r * lda + k0 + seg * 8;
            cp16(sAh + so, aAh + ga);
            cp16(sAl + so, aAl + ga);
        }
#pragma unroll
        for (int it = 0; it < 4; ++it) {             // B: 256 rows x 4 segs
            const int slot = tid + it * 256;         // 0..1023
            const int r    = slot >> 2;
            const int seg  = slot & 3;
            const uint32_t so = sw64((uint32_t)(r * ROWB + seg * 16));
            const size_t gb = (size_t)r * ldb + k0 + seg * 8;
            cp16(sBh + so, aBh + gb);
            cp16(sBl + so, aBl + gb);
        }
        CP_COMMIT();
    };

    float acc[4][8][4];
#pragma unroll
    for (int mt = 0; mt < 4; ++mt)
#pragma unroll
        for (int nt = 0; nt < 8; ++nt)
#pragma unroll
            for (int e = 0; e < 4; ++e) acc[mt][nt][e] = 0.f;

    // Prologue: chunks 0 and 1
    load_chunk(0, base + 0 * STAGE_B);
    load_chunk(BKC, base + 1 * STAGE_B);

    // Per-lane intra-tile offsets (validated fragment mapping; 64B rows)
    const uint32_t aRow = (uint32_t)(wm * 64 + (lane & 15));                 // + mt*16
    const uint32_t aCb  = (uint32_t)((lane >> 4) << 4);                      // + kk*32
    const uint32_t bRow = (uint32_t)(wn * 64 + ((lane >> 4) << 3) + (lane & 7)); // + j*16
    const uint32_t bCb  = (uint32_t)(((lane >> 3) & 1) << 4);                // + kk*32

#pragma unroll 1
    for (int i = 0; i < NCHUNK; ++i) {
        if (i + 1 < NCHUNK) { CP_WAIT(1); } else { CP_WAIT(0); }
        __syncthreads();

        if (i + 2 < NCHUNK)
            load_chunk((i + 2) * BKC, base + ((i + 2) % NSTAGE) * STAGE_B);

        const uint32_t stg = base + (i % NSTAGE) * STAGE_B;
        const uint32_t sAh = stg;
        const uint32_t sAl = stg + TILEA_B;
        const uint32_t sBh = stg + 2 * TILEA_B;
        const uint32_t sBl = stg + 2 * TILEA_B + TILEB_B;

#pragma unroll
        for (int kk = 0; kk < 2; ++kk) {          // 2 x k16 = 32
            uint32_t bh[8][2], bl[8][2];
#pragma unroll
            for (int j = 0; j < 4; ++j) {
                const uint32_t off = sw64((bRow + j * 16) * ROWB + kk * 32 + bCb);
                uint32_t t[4];
                ldsm4(t, sBh + off);
                bh[j*2][0] = t[0]; bh[j*2][1] = t[1];
                bh[j*2+1][0] = t[2]; bh[j*2+1][1] = t[3];
                ldsm4(t, sBl + off);
                bl[j*2][0] = t[0]; bl[j*2][1] = t[1];
                bl[j*2+1][0] = t[2]; bl[j*2+1][1] = t[3];
            }
            // Per mt: ah products (ah dies), then al products
#pragma unroll
            for (int mt = 0; mt < 4; ++mt) {
                const uint32_t offA = sw64((aRow + mt * 16) * ROWB + kk * 32 + aCb);
                uint32_t ah[4];
                ldsm4(ah, sAh + offA);
#pragma unroll
                for (int nt = 0; nt < 8; ++nt) mma_bf16(acc[mt][nt], ah, bh[nt]);
#pragma unroll
                for (int nt = 0; nt < 8; ++nt) mma_bf16(acc[mt][nt], ah, bl[nt]);
                uint32_t al[4];
                ldsm4(al, sAl + offA);
#pragma unroll
                for (int nt = 0; nt < 8; ++nt) mma_bf16(acc[mt][nt], al, bh[nt]);
            }
        }
    }

    // ---- Epilogue: registers -> global ----
    const int l4 = lane >> 2;
    const int l2 = (lane & 3) * 2;
#pragma unroll
    for (int mt = 0; mt < 4; ++mt) {
#pragma unroll
        for (int half = 0; half < 2; ++half) {
            const int r = rowBase + wm * 64 + mt * 16 + l4 + half * 8;
            float rbias = 0.f;
            if (BIAS_MODE == 2) rbias = __ldg(&bias[r]);
#pragma unroll
            for (int nt = 0; nt < 8; ++nt) {
                const int c = colBase + wn * 64 + nt * 8 + l2;
                float v0 = acc[mt][nt][half * 2 + 0];
                float v1 = acc[mt][nt][half * 2 + 1];
                if (BIAS_MODE == 1) {
                    float2 bv = *reinterpret_cast<const float2*>(&bias[c]);
                    v0 += bv.x; v1 += bv.y;
                } else if (BIAS_MODE == 2) {
                    v0 += rbias; v1 += rbias;
                }
                if (OUT_SPLIT == 0) {
                    float2 st; st.x = v0; st.y = v1;
                    *reinterpret_cast<float2*>(Cf + (size_t)r * ldc + c) = st;
                } else {
                    __nv_bfloat16 h0 = __float2bfloat16(v0);
                    __nv_bfloat16 h1 = __float2bfloat16(v1);
                    __nv_bfloat16 q0 = __float2bfloat16(v0 - __bfloat162float(h0));
                    __nv_bfloat16 q1 = __float2bfloat16(v1 - __bfloat162float(h1));
                    *reinterpret_cast<__nv_bfloat162*>(Ch + (size_t)r * ldc + c) =
                        __halves2bfloat162(h0, h1);
                    *reinterpret_cast<__nv_bfloat162*>(Cl + (size_t)r * ldc + c) =
                        __halves2bfloat162(q0, q1);
                }
            }
        }
    }
}

// ============================================================================
// Row softmax over 1024-wide rows; fp32 in, bf16 hi/lo split out.
// ============================================================================
__global__ void __launch_bounds__(256)
softmax_split(const float* __restrict__ S, __nv_bfloat16* __restrict__ Ph,
              __nv_bfloat16* __restrict__ Pl)
{
    const int row = blockIdx.x;
    const int t = threadIdx.x;
    const int w = t >> 5, l = t & 31;

    float4 v = *reinterpret_cast<const float4*>(S + (size_t)row * 1024 + t * 4);

    float m = fmaxf(fmaxf(v.x, v.y), fmaxf(v.z, v.w));
#pragma unroll
    for (int o = 16; o; o >>= 1) m = fmaxf(m, __shfl_xor_sync(0xffffffffu, m, o));

    __shared__ float redm[8], reds[8];
    if (l == 0) redm[w] = m;
    __syncthreads();
    float rm = fmaxf(fmaxf(fmaxf(redm[0], redm[1]), fmaxf(redm[2], redm[3])),
                     fmaxf(fmaxf(redm[4], redm[5]), fmaxf(redm[6], redm[7])));

    v.x = __expf(v.x - rm);
    v.y = __expf(v.y - rm);
    v.z = __expf(v.z - rm);
    v.w = __expf(v.w - rm);

    float s = v.x + v.y + v.z + v.w;
#pragma unroll
    for (int o = 16; o; o >>= 1) s += __shfl_xor_sync(0xffffffffu, s, o);
    if (l == 0) reds[w] = s;
    __syncthreads();
    float tot = (reds[0] + reds[1]) + (reds[2] + reds[3])
              + (reds[4] + reds[5]) + (reds[6] + reds[7]);

    const float inv = 1.0f / tot;
    float w0 = v.x * inv, w1 = v.y * inv, w2 = v.z * inv, w3 = v.w * inv;

    __nv_bfloat16 h0 = __float2bfloat16(w0), h1 = __float2bfloat16(w1);
    __nv_bfloat16 h2 = __float2bfloat16(w2), h3 = __float2bfloat16(w3);
    __nv_bfloat16 l0 = __float2bfloat16(w0 - __bfloat162float(h0));
    __nv_bfloat16 l1 = __float2bfloat16(w1 - __bfloat162float(h1));
    __nv_bfloat16 l2 = __float2bfloat16(w2 - __bfloat162float(h2));
    __nv_bfloat16 l3 = __float2bfloat16(w3 - __bfloat162float(h3));

    const size_t p2 = ((size_t)row * 1024 + t * 4) >> 1;
    reinterpret_cast<__nv_bfloat162*>(Ph)[p2 + 0] = __halves2bfloat162(h0, h1);
    reinterpret_cast<__nv_bfloat162*>(Ph)[p2 + 1] = __halves2bfloat162(h2, h3);
    reinterpret_cast<__nv_bfloat162*>(Pl)[p2 + 0] = __halves2bfloat162(l0, l1);
    reinterpret_cast<__nv_bfloat162*>(Pl)[p2 + 1] = __halves2bfloat162(l2, l3);
}

// ============================================================================
// kernel_launch — splits hoisted so launch #6 is a GEMM (ncu -s 5 -c 1)
// ============================================================================
extern "C" void kernel_launch(void* const* d_in, const int* in_sizes, int n_in,
                              void* d_out, int out_size)
{
    const float* meme  = (const float*)d_in[0];
    const float* text  = (const float*)d_in[1];
    const float* emoji = (const float*)d_in[2];
    const float* Wq    = (const float*)d_in[3];
    const float* bq    = (const float*)d_in[4];
    const float* Wk    = (const float*)d_in[5];
    const float* bk    = (const float*)d_in[6];
    const float* Wv    = (const float*)d_in[7];
    const float* bv    = (const float*)d_in[8];
    float* out = (float*)d_out;

    __nv_bfloat16 *Xmh,*Xml,*Xth,*Xtl,*Xeh,*Xel,*Wqh,*Wql,*Wkh,*Wkl,*Wvh,*Wvl;
    __nv_bfloat16 *Qh,*Ql,*Kh,*Kl,*VTh,*VTl,*Ph,*Pl;
    float* S;
    cudaGetSymbolAddress((void**)&Xmh, g_Xmh); cudaGetSymbolAddress((void**)&Xml, g_Xml);
    cudaGetSymbolAddress((void**)&Xth, g_Xth); cudaGetSymbolAddress((void**)&Xtl, g_Xtl);
    cudaGetSymbolAddress((void**)&Xeh, g_Xeh); cudaGetSymbolAddress((void**)&Xel, g_Xel);
    cudaGetSymbolAddress((void**)&Wqh, g_Wqh); cudaGetSymbolAddress((void**)&Wql, g_Wql);
    cudaGetSymbolAddress((void**)&Wkh, g_Wkh); cudaGetSymbolAddress((void**)&Wkl, g_Wkl);
    cudaGetSymbolAddress((void**)&Wvh, g_Wvh); cudaGetSymbolAddress((void**)&Wvl, g_Wvl);
    cudaGetSymbolAddress((void**)&Qh, g_Qh);   cudaGetSymbolAddress((void**)&Ql, g_Ql);
    cudaGetSymbolAddress((void**)&Kh, g_Kh);   cudaGetSymbolAddress((void**)&Kl, g_Kl);
    cudaGetSymbolAddress((void**)&VTh, g_VTh); cudaGetSymbolAddress((void**)&VTl, g_VTl);
    cudaGetSymbolAddress((void**)&Ph, g_Ph);   cudaGetSymbolAddress((void**)&Pl, g_Pl);
    cudaGetSymbolAddress((void**)&S, g_S);

    cudaFuncSetAttribute(gemm_split<1, 1>, cudaFuncAttributeMaxDynamicSharedMemorySize, GEMM_SMEM);
    cudaFuncSetAttribute(gemm_split<2, 1>, cudaFuncAttributeMaxDynamicSharedMemorySize, GEMM_SMEM);
    cudaFuncSetAttribute(gemm_split<0, 0>, cudaFuncAttributeMaxDynamicSharedMemorySize, GEMM_SMEM);

    const size_t bstr = (size_t)SEQ * HID;          // 1M elems per batch
    const int nx4 = (MTOT * HID) / 4;
    const int nw4 = (HID * HID) / 4;

    dim3 blk(256);
    dim3 gProj(HID / 256, MTOT / 128, 1);           // (4, 128)
    dim3 gVT(MTOT / 256, HID / 128, 1);             // (64, 8)
    dim3 gAtt(SEQ / 256, SEQ / 128, NBAT);          // (4, 8, 16)

    // Launches 1-5: splits (W splits tiny; X meme/text)
    f32_to_split<<<(nw4 + 255) / 256, blk>>>(Wq, Wqh, Wql, nw4);     // 1
    f32_to_split<<<(nw4 + 255) / 256, blk>>>(Wk, Wkh, Wkl, nw4);     // 2
    f32_to_split<<<(nw4 + 255) / 256, blk>>>(Wv, Wvh, Wvl, nw4);     // 3
    f32_to_split<<<(nx4 + 255) / 256, blk>>>(meme, Xmh, Xml, nx4);   // 4
    f32_to_split<<<(nx4 + 255) / 256, blk>>>(text, Xth, Xtl, nx4);   // 5

    // Launch 6: Q projection GEMM  <- ncu capture target
    gemm_split<1, 1><<<gProj, blk, GEMM_SMEM>>>(Xmh, Xml, HID, 0, Wqh, Wql, HID, 0,
                                                bq, nullptr, Qh, Ql, HID, 0);
    // 7: emoji split
    f32_to_split<<<(nx4 + 255) / 256, blk>>>(emoji, Xeh, Xel, nx4);
    // 8: K projection
    gemm_split<1, 1><<<gProj, blk, GEMM_SMEM>>>(Xth, Xtl, HID, 0, Wkh, Wkl, HID, 0,
                                                bk, nullptr, Kh, Kl, HID, 0);
    // 9: V^T projection: VT[a][lg] = Wv[a][:] . emoji[lg][:] + bv[a]  (ldc=16384)
    gemm_split<2, 1><<<gVT, blk, GEMM_SMEM>>>(Wvh, Wvl, HID, 0, Xeh, Xel, HID, 0,
                                              bv, nullptr, VTh, VTl, MTOT, 0);
    // 10: scores per batch  S[q][k] = Q[q][:] . K[k][:]
    gemm_split<0, 0><<<gAtt, blk, GEMM_SMEM>>>(Qh, Ql, HID, bstr, Kh, Kl, HID, bstr,
                                               nullptr, S, nullptr, nullptr, SEQ, bstr);
    // 11: softmax -> split weights
    softmax_split<<<MTOT, blk>>>(S, Ph, Pl);
    // 12: output per batch  O[q][a] = P[q][:] . VT[a][b*1024 + :]
    gemm_split<0, 0><<<gAtt, blk, GEMM_SMEM>>>(Ph, Pl, SEQ, bstr,
                                               VTh, VTl, MTOT, (size_t)SEQ,
                                               nullptr, out, nullptr, nullptr, HID, bstr);
}

// round 11
// speedup vs baseline: 1.2053x; 1.2053x over previous
#include <cuda_runtime.h>
#include <cuda_bf16.h>
#include <cstdint>

// Problem dims (fixed)
#define HID   1024
#define NBAT  16
#define SEQ   1024
#define MTOT  (NBAT * SEQ)        // 16384

// ============================================================================
// PTX helpers available on base sm_103 target
// ============================================================================
__device__ __forceinline__ uint32_t smem_u32_of(const void* p) {
    uint32_t a;
    asm("{ .reg .u64 t; cvta.to.shared.u64 t, %1; cvt.u32.u64 %0, t; }"
        : "=r"(a) : "l"(p));
    return a;
}

__device__ __forceinline__ void cp16(uint32_t s, const void* g) {
    asm volatile("cp.async.cg.shared.global [%0], [%1], 16;" :: "r"(s), "l"(g));
}
#define CP_COMMIT() asm volatile("cp.async.commit_group;" ::: "memory")
#define CP_WAIT(N)  asm volatile("cp.async.wait_group %0;" :: "n"(N) : "memory")

__device__ __forceinline__ void ldsm4(uint32_t* r, uint32_t addr) {
    asm volatile("ldmatrix.sync.aligned.m8n8.x4.shared.b16 {%0,%1,%2,%3}, [%4];"
        : "=r"(r[0]), "=r"(r[1]), "=r"(r[2]), "=r"(r[3]) : "r"(addr));
}

__device__ __forceinline__ void mma_bf16(float* c, const uint32_t* a, const uint32_t* b) {
    asm volatile(
        "mma.sync.aligned.m16n8k16.row.col.f32.bf16.bf16.f32 "
        "{%0,%1,%2,%3}, {%4,%5,%6,%7}, {%8,%9}, {%0,%1,%2,%3};"
        : "+f"(c[0]), "+f"(c[1]), "+f"(c[2]), "+f"(c[3])
        : "r"(a[0]), "r"(a[1]), "r"(a[2]), "r"(a[3]), "r"(b[0]), "r"(b[1]));
}

// Conflict-free swizzle for 64-byte smem rows (validated R8)
__device__ __forceinline__ uint32_t sw64(uint32_t o) { return o ^ ((o >> 3) & 0x30); }

// ============================================================================
// Device global scratch (per-input buffers so splits can run concurrently)
// ============================================================================
__device__ __align__(16) __nv_bfloat16 g_Xmh[MTOT * HID], g_Xml[MTOT * HID];
__device__ __align__(16) __nv_bfloat16 g_Xth[MTOT * HID], g_Xtl[MTOT * HID];
__device__ __align__(16) __nv_bfloat16 g_Xeh[MTOT * HID], g_Xel[MTOT * HID];
__device__ __align__(16) __nv_bfloat16 g_Wqh[HID * HID],  g_Wql[HID * HID];
__device__ __align__(16) __nv_bfloat16 g_Wkh[HID * HID],  g_Wkl[HID * HID];
__device__ __align__(16) __nv_bfloat16 g_Wvh[HID * HID],  g_Wvl[HID * HID];
__device__ __align__(16) __nv_bfloat16 g_Qh[MTOT * HID],  g_Ql[MTOT * HID];
__device__ __align__(16) __nv_bfloat16 g_Kh[MTOT * HID],  g_Kl[MTOT * HID];
__device__ __align__(16) __nv_bfloat16 g_VTh[MTOT * HID], g_VTl[MTOT * HID]; // ld=16384
__device__ __align__(16) float         g_S [MTOT * SEQ];
__device__ __align__(16) __nv_bfloat16 g_Ph[MTOT * SEQ],  g_Pl[MTOT * SEQ];

// ============================================================================
// fp32 -> (bf16 hi, bf16 lo) split, 4 float4 per thread (MLP 4)
// ============================================================================
__global__ void __launch_bounds__(256)
f32_to_split(const float* __restrict__ x, __nv_bfloat16* __restrict__ h,
             __nv_bfloat16* __restrict__ l, int n4)
{
    const int base = blockIdx.x * 1024 + threadIdx.x;
    float4 v[4];
#pragma unroll
    for (int u = 0; u < 4; ++u) {
        const int i = base + u * 256;
        v[u] = (i < n4) ? reinterpret_cast<const float4*>(x)[i]
                        : make_float4(0.f, 0.f, 0.f, 0.f);
    }
#pragma unroll
    for (int u = 0; u < 4; ++u) {
        const int i = base + u * 256;
        if (i >= n4) continue;
        __nv_bfloat16 h0 = __float2bfloat16(v[u].x);
        __nv_bfloat16 h1 = __float2bfloat16(v[u].y);
        __nv_bfloat16 h2 = __float2bfloat16(v[u].z);
        __nv_bfloat16 h3 = __float2bfloat16(v[u].w);
        __nv_bfloat16 l0 = __float2bfloat16(v[u].x - __bfloat162float(h0));
        __nv_bfloat16 l1 = __float2bfloat16(v[u].y - __bfloat162float(h1));
        __nv_bfloat16 l2 = __float2bfloat16(v[u].z - __bfloat162float(h2));
        __nv_bfloat16 l3 = __float2bfloat16(v[u].w - __bfloat162float(h3));
        reinterpret_cast<__nv_bfloat162*>(h)[2 * i + 0] = __halves2bfloat162(h0, h1);
        reinterpret_cast<__nv_bfloat162*>(h)[2 * i + 1] = __halves2bfloat162(h2, h3);
        reinterpret_cast<__nv_bfloat162*>(l)[2 * i + 0] = __halves2bfloat162(l0, l1);
        reinterpret_cast<__nv_bfloat162*>(l)[2 * i + 1] = __halves2bfloat162(l2, l3);
    }
}

// ============================================================================
// Split-bf16 NT GEMM on mma.sync (HMMA) — R8 best config (BK=32, sw64, occ 2)
//   D[m][n] = sum_k A[m][k]*B[n][k]  (hi*hi + hi*lo + lo*hi, fp32 accum)
//   BIAS_MODE: 0 none, 1 per-col bias[n], 2 per-row bias[m]
//   OUT_SPLIT: 0 -> fp32 Cf;  1 -> bf16 pair (Ch, Cl)
// ============================================================================
#define KDEPTH   1024
#define BKC      32
#define NCHUNK   (KDEPTH / BKC)     // 32
#define ROWB     64                 // bytes per smem row
#define TILE_B   8192               // 128 rows x 64 B
#define STAGE_B  (4 * TILE_B)       // Ah, Al, Bh, Bl = 32 KB
#define NSTAGE   3
#define GEMM_SMEM (1024 + NSTAGE * STAGE_B)   // ~97 KB -> 2 CTAs/SM

template<int BIAS_MODE, int OUT_SPLIT>
__global__ void __launch_bounds__(256, 2)
gemm_split(const __nv_bfloat16* __restrict__ Ah, const __nv_bfloat16* __restrict__ Al,
           int lda, size_t sA,
           const __nv_bfloat16* __restrict__ Bh, const __nv_bfloat16* __restrict__ Bl,
           int ldb, size_t sB,
           const float* __restrict__ bias,
           float* __restrict__ Cf, __nv_bfloat16* __restrict__ Ch,
           __nv_bfloat16* __restrict__ Cl,
           int ldc, size_t sC)
{
    extern __shared__ char smem[];
    const int tid  = threadIdx.x;
    const int wid  = tid >> 5;
    const int lane = tid & 31;
    const int wm   = wid >> 2;     // 0..1  (M)
    const int wn   = wid & 3;      // 0..3  (N)
    const int z    = blockIdx.z;

    Ah += (size_t)z * sA;  Al += (size_t)z * sA;
    Bh += (size_t)z * sB;  Bl += (size_t)z * sB;
    if (OUT_SPLIT) { Ch += (size_t)z * sC; Cl += (size_t)z * sC; }
    else           { Cf += (size_t)z * sC; }

    const int rowBase = blockIdx.y * 128;
    const int colBase = blockIdx.x * 128;

    const uint32_t raw  = smem_u32_of(smem);
    const uint32_t base = (raw + 1023u) & ~1023u;

    const __nv_bfloat16* aAh = Ah + (size_t)rowBase * lda;
    const __nv_bfloat16* aAl = Al + (size_t)rowBase * lda;
    const __nv_bfloat16* aBh = Bh + (size_t)colBase * ldb;
    const __nv_bfloat16* aBl = Bl + (size_t)colBase * ldb;

    auto load_chunk = [&](int k0, uint32_t stg) {
#pragma unroll
        for (int it = 0; it < 2; ++it) {
            const int slot = tid + it * 256;     // 0..511
            const int r    = slot >> 2;          // 0..127
            const int seg  = slot & 3;           // 16B segment
            const uint32_t so = sw64((uint32_t)(r * ROWB + seg * 16));
            const size_t ga = (size_t)r * lda + k0 + seg * 8;
            const size_t gb = (size_t)r * ldb + k0 + seg * 8;
            cp16(stg + 0 * TILE_B + so, aAh + ga);
            cp16(stg + 1 * TILE_B + so, aAl + ga);
            cp16(stg + 2 * TILE_B + so, aBh + gb);
            cp16(stg + 3 * TILE_B + so, aBl + gb);
        }
        CP_COMMIT();
    };

    float acc[4][4][4];
#pragma unroll
    for (int mt = 0; mt < 4; ++mt)
#pragma unroll
        for (int nt = 0; nt < 4; ++nt)
#pragma unroll
            for (int e = 0; e < 4; ++e) acc[mt][nt][e] = 0.f;

    load_chunk(0, base + 0 * STAGE_B);
    load_chunk(BKC, base + 1 * STAGE_B);

    const uint32_t aRow = (uint32_t)(wm * 64 + (lane & 15));
    const uint32_t aCb  = (uint32_t)((lane >> 4) << 4);
    const uint32_t bRow = (uint32_t)(wn * 32 + ((lane >> 4) << 3) + (lane & 7));
    const uint32_t bCb  = (uint32_t)(((lane >> 3) & 1) << 4);

#pragma unroll 1
    for (int i = 0; i < NCHUNK; ++i) {
        if (i + 1 < NCHUNK) { CP_WAIT(1); } else { CP_WAIT(0); }
        __syncthreads();

        if (i + 2 < NCHUNK)
            load_chunk((i + 2) * BKC, base + ((i + 2) % NSTAGE) * STAGE_B);

        const uint32_t stg = base + (i % NSTAGE) * STAGE_B;
        const uint32_t sAh = stg;
        const uint32_t sAl = stg + 1 * TILE_B;
        const uint32_t sBh = stg + 2 * TILE_B;
        const uint32_t sBl = stg + 3 * TILE_B;

#pragma unroll
        for (int kk = 0; kk < 2; ++kk) {          // 2 x k16 = 32
            uint32_t bh[4][2], bl[4][2];
#pragma unroll
            for (int j = 0; j < 2; ++j) {
                const uint32_t off = sw64((bRow + j * 16) * ROWB + kk * 32 + bCb);
                uint32_t t[4];
                ldsm4(t, sBh + off);
                bh[j*2][0] = t[0]; bh[j*2][1] = t[1];
                bh[j*2+1][0] = t[2]; bh[j*2+1][1] = t[3];
                ldsm4(t, sBl + off);
                bl[j*2][0] = t[0]; bl[j*2][1] = t[1];
                bl[j*2+1][0] = t[2]; bl[j*2+1][1] = t[3];
            }
#pragma unroll
            for (int mt = 0; mt < 4; ++mt) {
                const uint32_t offA = sw64((aRow + mt * 16) * ROWB + kk * 32 + aCb);
                uint32_t ah[4];
                ldsm4(ah, sAh + offA);
#pragma unroll
                for (int nt = 0; nt < 4; ++nt) mma_bf16(acc[mt][nt], ah, bh[nt]);
#pragma unroll
                for (int nt = 0; nt < 4; ++nt) mma_bf16(acc[mt][nt], ah, bl[nt]);
                uint32_t al[4];
                ldsm4(al, sAl + offA);
#pragma unroll
                for (int nt = 0; nt < 4; ++nt) mma_bf16(acc[mt][nt], al, bh[nt]);
            }
        }
    }

    // ---- Epilogue ----
    const int l4 = lane >> 2;
    const int l2 = (lane & 3) * 2;
#pragma unroll
    for (int mt = 0; mt < 4; ++mt) {
#pragma unroll
        for (int half = 0; half < 2; ++half) {
            const int r = rowBase + wm * 64 + mt * 16 + l4 + half * 8;
            float rbias = 0.f;
            if (BIAS_MODE == 2) rbias = __ldg(&bias[r]);
#pragma unroll
            for (int nt = 0; nt < 4; ++nt) {
                const int c = colBase + wn * 32 + nt * 8 + l2;
                float v0 = acc[mt][nt][half * 2 + 0];
                float v1 = acc[mt][nt][half * 2 + 1];
                if (BIAS_MODE == 1) {
                    float2 bv = *reinterpret_cast<const float2*>(&bias[c]);
                    v0 += bv.x; v1 += bv.y;
                } else if (BIAS_MODE == 2) {
                    v0 += rbias; v1 += rbias;
                }
                if (OUT_SPLIT == 0) {
                    float2 st; st.x = v0; st.y = v1;
                    *reinterpret_cast<float2*>(Cf + (size_t)r * ldc + c) = st;
                } else {
                    __nv_bfloat16 h0 = __float2bfloat16(v0);
                    __nv_bfloat16 h1 = __float2bfloat16(v1);
                    __nv_bfloat16 q0 = __float2bfloat16(v0 - __bfloat162float(h0));
                    __nv_bfloat16 q1 = __float2bfloat16(v1 - __bfloat162float(h1));
                    *reinterpret_cast<__nv_bfloat162*>(Ch + (size_t)r * ldc + c) =
                        __halves2bfloat162(h0, h1);
                    *reinterpret_cast<__nv_bfloat162*>(Cl + (size_t)r * ldc + c) =
                        __halves2bfloat162(q0, q1);
                }
            }
        }
    }
}

// ============================================================================
// Row softmax over 1024-wide rows; fp32 in, bf16 hi/lo split out.
// ============================================================================
__global__ void __launch_bounds__(256)
softmax_split(const float* __restrict__ S, __nv_bfloat16* __restrict__ Ph,
              __nv_bfloat16* __restrict__ Pl)
{
    const int row = blockIdx.x;
    const int t = threadIdx.x;
    const int w = t >> 5, l = t & 31;

    float4 v = *reinterpret_cast<const float4*>(S + (size_t)row * 1024 + t * 4);

    float m = fmaxf(fmaxf(v.x, v.y), fmaxf(v.z, v.w));
#pragma unroll
    for (int o = 16; o; o >>= 1) m = fmaxf(m, __shfl_xor_sync(0xffffffffu, m, o));

    __shared__ float redm[8], reds[8];
    if (l == 0) redm[w] = m;
    __syncthreads();
    float rm = fmaxf(fmaxf(fmaxf(redm[0], redm[1]), fmaxf(redm[2], redm[3])),
                     fmaxf(fmaxf(redm[4], redm[5]), fmaxf(redm[6], redm[7])));

    v.x = __expf(v.x - rm);
    v.y = __expf(v.y - rm);
    v.z = __expf(v.z - rm);
    v.w = __expf(v.w - rm);

    float s = v.x + v.y + v.z + v.w;
#pragma unroll
    for (int o = 16; o; o >>= 1) s += __shfl_xor_sync(0xffffffffu, s, o);
    if (l == 0) reds[w] = s;
    __syncthreads();
    float tot = (reds[0] + reds[1]) + (reds[2] + reds[3])
              + (reds[4] + reds[5]) + (reds[6] + reds[7]);

    const float inv = 1.0f / tot;
    float w0 = v.x * inv, w1 = v.y * inv, w2 = v.z * inv, w3 = v.w * inv;

    __nv_bfloat16 h0 = __float2bfloat16(w0), h1 = __float2bfloat16(w1);
    __nv_bfloat16 h2 = __float2bfloat16(w2), h3 = __float2bfloat16(w3);
    __nv_bfloat16 l0 = __float2bfloat16(w0 - __bfloat162float(h0));
    __nv_bfloat16 l1 = __float2bfloat16(w1 - __bfloat162float(h1));
    __nv_bfloat16 l2 = __float2bfloat16(w2 - __bfloat162float(h2));
    __nv_bfloat16 l3 = __float2bfloat16(w3 - __bfloat162float(h3));

    const size_t p2 = ((size_t)row * 1024 + t * 4) >> 1;
    reinterpret_cast<__nv_bfloat162*>(Ph)[p2 + 0] = __halves2bfloat162(h0, h1);
    reinterpret_cast<__nv_bfloat162*>(Ph)[p2 + 1] = __halves2bfloat162(h2, h3);
    reinterpret_cast<__nv_bfloat162*>(Pl)[p2 + 0] = __halves2bfloat162(l0, l1);
    reinterpret_cast<__nv_bfloat162*>(Pl)[p2 + 1] = __halves2bfloat162(l2, l3);
}

// ============================================================================
// kernel_launch — side stream hides the independent splits behind Q-proj.
// Stream/events are created once (host objects, no device allocation).
// ============================================================================
extern "C" void kernel_launch(void* const* d_in, const int* in_sizes, int n_in,
                              void* d_out, int out_size)
{
    const float* meme  = (const float*)d_in[0];
    const float* text  = (const float*)d_in[1];
    const float* emoji = (const float*)d_in[2];
    const float* Wq    = (const float*)d_in[3];
    const float* bq    = (const float*)d_in[4];
    const float* Wk    = (const float*)d_in[5];
    const float* bk    = (const float*)d_in[6];
    const float* Wv    = (const float*)d_in[7];
    const float* bv    = (const float*)d_in[8];
    float* out = (float*)d_out;

    __nv_bfloat16 *Xmh,*Xml,*Xth,*Xtl,*Xeh,*Xel,*Wqh,*Wql,*Wkh,*Wkl,*Wvh,*Wvl;
    __nv_bfloat16 *Qh,*Ql,*Kh,*Kl,*VTh,*VTl,*Ph,*Pl;
    float* S;
    cudaGetSymbolAddress((void**)&Xmh, g_Xmh); cudaGetSymbolAddress((void**)&Xml, g_Xml);
    cudaGetSymbolAddress((void**)&Xth, g_Xth); cudaGetSymbolAddress((void**)&Xtl, g_Xtl);
    cudaGetSymbolAddress((void**)&Xeh, g_Xeh); cudaGetSymbolAddress((void**)&Xel, g_Xel);
    cudaGetSymbolAddress((void**)&Wqh, g_Wqh); cudaGetSymbolAddress((void**)&Wql, g_Wql);
    cudaGetSymbolAddress((void**)&Wkh, g_Wkh); cudaGetSymbolAddress((void**)&Wkl, g_Wkl);
    cudaGetSymbolAddress((void**)&Wvh, g_Wvh); cudaGetSymbolAddress((void**)&Wvl, g_Wvl);
    cudaGetSymbolAddress((void**)&Qh, g_Qh);   cudaGetSymbolAddress((void**)&Ql, g_Ql);
    cudaGetSymbolAddress((void**)&Kh, g_Kh);   cudaGetSymbolAddress((void**)&Kl, g_Kl);
    cudaGetSymbolAddress((void**)&VTh, g_VTh); cudaGetSymbolAddress((void**)&VTl, g_VTl);
    cudaGetSymbolAddress((void**)&Ph, g_Ph);   cudaGetSymbolAddress((void**)&Pl, g_Pl);
    cudaGetSymbolAddress((void**)&S, g_S);

    static bool inited = false;
    static cudaStream_t s1;
    static cudaEvent_t evFork, evJoin;
    if (!inited) {
        cudaStreamCreateWithFlags(&s1, cudaStreamNonBlocking);
        cudaEventCreateWithFlags(&evFork, cudaEventDisableTiming);
        cudaEventCreateWithFlags(&evJoin, cudaEventDisableTiming);
        cudaFuncSetAttribute(gemm_split<1, 1>, cudaFuncAttributeMaxDynamicSharedMemorySize, GEMM_SMEM);
        cudaFuncSetAttribute(gemm_split<2, 1>, cudaFuncAttributeMaxDynamicSharedMemorySize, GEMM_SMEM);
        cudaFuncSetAttribute(gemm_split<0, 0>, cudaFuncAttributeMaxDynamicSharedMemorySize, GEMM_SMEM);
        inited = true;
    }

    const size_t bstr = (size_t)SEQ * HID;          // 1M elems per batch
    const int nx4 = (MTOT * HID) / 4;
    const int nw4 = (HID * HID) / 4;
    const int gX = (nx4 + 1023) / 1024;             // split grid (4 f4/thread)
    const int gW = (nw4 + 1023) / 1024;

    dim3 blk(256);
    dim3 gProj(HID / 128, MTOT / 128, 1);           // (8, 128)
    dim3 gVT(MTOT / 128, HID / 128, 1);             // (128, 8)
    dim3 gAtt(SEQ / 128, SEQ / 128, NBAT);          // (8, 8, 16)

    // Fork: side stream handles the splits not needed by the first GEMM.
    cudaEventRecord(evFork, 0);
    cudaStreamWaitEvent(s1, evFork, 0);
    f32_to_split<<<gW, blk, 0, s1>>>(Wk, Wkh, Wkl, nw4);
    f32_to_split<<<gX, blk, 0, s1>>>(text, Xth, Xtl, nx4);
    f32_to_split<<<gW, blk, 0, s1>>>(Wv, Wvh, Wvl, nw4);
    f32_to_split<<<gX, blk, 0, s1>>>(emoji, Xeh, Xel, nx4);
    cudaEventRecord(evJoin, s1);

    // Main stream: Q-proj dependencies, then Q-proj (overlaps side splits).
    f32_to_split<<<gW, blk>>>(Wq, Wqh, Wql, nw4);
    f32_to_split<<<gX, blk>>>(meme, Xmh, Xml, nx4);
    gemm_split<1, 1><<<gProj, blk, GEMM_SMEM>>>(Xmh, Xml, HID, 0, Wqh, Wql, HID, 0,
                                                bq, nullptr, Qh, Ql, HID, 0);

    // Join before consuming side-stream outputs.
    cudaStreamWaitEvent(0, evJoin, 0);

    // K projection
    gemm_split<1, 1><<<gProj, blk, GEMM_SMEM>>>(Xth, Xtl, HID, 0, Wkh, Wkl, HID, 0,
                                                bk, nullptr, Kh, Kl, HID, 0);
    // V^T projection: VT[a][lg] = Wv[a][:] . emoji[lg][:] + bv[a]  (ldc=16384)
    gemm_split<2, 1><<<gVT, blk, GEMM_SMEM>>>(Wvh, Wvl, HID, 0, Xeh, Xel, HID, 0,
                                              bv, nullptr, VTh, VTl, MTOT, 0);
    // Scores: per batch  S[q][k] = Q[q][:] . K[k][:]
    gemm_split<0, 0><<<gAtt, blk, GEMM_SMEM>>>(Qh, Ql, HID, bstr, Kh, Kl, HID, bstr,
                                               nullptr, S, nullptr, nullptr, SEQ, bstr);
    // Softmax -> split weights
    softmax_split<<<MTOT, blk>>>(S, Ph, Pl);
    // Output: per batch  O[q][a] = P[q][:] . VT[a][b*1024 + :]
    gemm_split<0, 0><<<gAtt, blk, GEMM_SMEM>>>(Ph, Pl, SEQ, bstr,
                                               VTh, VTl, MTOT, (size_t)SEQ,
                                               nullptr, out, nullptr, nullptr, HID, bstr);
}

// round 12
// speedup vs baseline: 1.2479x; 1.0353x over previous
#include <cuda_runtime.h>
#include <cuda_bf16.h>
#include <cstdint>

// Problem dims (fixed)
#define HID   1024
#define NBAT  16
#define SEQ   1024
#define MTOT  (NBAT * SEQ)        // 16384

// ============================================================================
// PTX helpers available on base sm_103 target
// ============================================================================
__device__ __forceinline__ uint32_t smem_u32_of(const void* p) {
    uint32_t a;
    asm("{ .reg .u64 t; cvta.to.shared.u64 t, %1; cvt.u32.u64 %0, t; }"
        : "=r"(a) : "l"(p));
    return a;
}

__device__ __forceinline__ void cp16(uint32_t s, const void* g) {
    asm volatile("cp.async.cg.shared.global [%0], [%1], 16;" :: "r"(s), "l"(g));
}
#define CP_COMMIT() asm volatile("cp.async.commit_group;" ::: "memory")
#define CP_WAIT(N)  asm volatile("cp.async.wait_group %0;" :: "n"(N) : "memory")

__device__ __forceinline__ void ldsm4(uint32_t* r, uint32_t addr) {
    asm volatile("ldmatrix.sync.aligned.m8n8.x4.shared.b16 {%0,%1,%2,%3}, [%4];"
        : "=r"(r[0]), "=r"(r[1]), "=r"(r[2]), "=r"(r[3]) : "r"(addr));
}

__device__ __forceinline__ void mma_bf16(float* c, const uint32_t* a, const uint32_t* b) {
    asm volatile(
        "mma.sync.aligned.m16n8k16.row.col.f32.bf16.bf16.f32 "
        "{%0,%1,%2,%3}, {%4,%5,%6,%7}, {%8,%9}, {%0,%1,%2,%3};"
        : "+f"(c[0]), "+f"(c[1]), "+f"(c[2]), "+f"(c[3])
        : "r"(a[0]), "r"(a[1]), "r"(a[2]), "r"(a[3]), "r"(b[0]), "r"(b[1]));
}

// Conflict-free swizzle for 64-byte smem rows (validated R8)
__device__ __forceinline__ uint32_t sw64(uint32_t o) { return o ^ ((o >> 3) & 0x30); }

// ============================================================================
// Device global scratch (per-input buffers so paths can run concurrently)
// ============================================================================
__device__ __align__(16) __nv_bfloat16 g_Xmh[MTOT * HID], g_Xml[MTOT * HID];
__device__ __align__(16) __nv_bfloat16 g_Xth[MTOT * HID], g_Xtl[MTOT * HID];
__device__ __align__(16) __nv_bfloat16 g_Xeh[MTOT * HID], g_Xel[MTOT * HID];
__device__ __align__(16) __nv_bfloat16 g_Wqh[HID * HID],  g_Wql[HID * HID];
__device__ __align__(16) __nv_bfloat16 g_Wkh[HID * HID],  g_Wkl[HID * HID];
__device__ __align__(16) __nv_bfloat16 g_Wvh[HID * HID],  g_Wvl[HID * HID];
__device__ __align__(16) __nv_bfloat16 g_Qh[MTOT * HID],  g_Ql[MTOT * HID];
__device__ __align__(16) __nv_bfloat16 g_Kh[MTOT * HID],  g_Kl[MTOT * HID];
__device__ __align__(16) __nv_bfloat16 g_VTh[MTOT * HID], g_VTl[MTOT * HID]; // ld=16384
__device__ __align__(16) float         g_S [MTOT * SEQ];
__device__ __align__(16) __nv_bfloat16 g_Ph[MTOT * SEQ],  g_Pl[MTOT * SEQ];

// ============================================================================
// fp32 -> (bf16 hi, bf16 lo) split, 4 float4 per thread (MLP 4)
// ============================================================================
__global__ void __launch_bounds__(256)
f32_to_split(const float* __restrict__ x, __nv_bfloat16* __restrict__ h,
             __nv_bfloat16* __restrict__ l, int n4)
{
    const int base = blockIdx.x * 1024 + threadIdx.x;
    float4 v[4];
#pragma unroll
    for (int u = 0; u < 4; ++u) {
        const int i = base + u * 256;
        v[u] = (i < n4) ? reinterpret_cast<const float4*>(x)[i]
                        : make_float4(0.f, 0.f, 0.f, 0.f);
    }
#pragma unroll
    for (int u = 0; u < 4; ++u) {
        const int i = base + u * 256;
        if (i >= n4) continue;
        __nv_bfloat16 h0 = __float2bfloat16(v[u].x);
        __nv_bfloat16 h1 = __float2bfloat16(v[u].y);
        __nv_bfloat16 h2 = __float2bfloat16(v[u].z);
        __nv_bfloat16 h3 = __float2bfloat16(v[u].w);
        __nv_bfloat16 l0 = __float2bfloat16(v[u].x - __bfloat162float(h0));
        __nv_bfloat16 l1 = __float2bfloat16(v[u].y - __bfloat162float(h1));
        __nv_bfloat16 l2 = __float2bfloat16(v[u].z - __bfloat162float(h2));
        __nv_bfloat16 l3 = __float2bfloat16(v[u].w - __bfloat162float(h3));
        reinterpret_cast<__nv_bfloat162*>(h)[2 * i + 0] = __halves2bfloat162(h0, h1);
        reinterpret_cast<__nv_bfloat162*>(h)[2 * i + 1] = __halves2bfloat162(h2, h3);
        reinterpret_cast<__nv_bfloat162*>(l)[2 * i + 0] = __halves2bfloat162(l0, l1);
        reinterpret_cast<__nv_bfloat162*>(l)[2 * i + 1] = __halves2bfloat162(l2, l3);
    }
}

// ============================================================================
// Split-bf16 NT GEMM on mma.sync (HMMA) — R8 best config (BK=32, sw64, occ 2)
//   D[m][n] = sum_k A[m][k]*B[n][k]  (hi*hi + hi*lo + lo*hi, fp32 accum)
//   BIAS_MODE: 0 none, 1 per-col bias[n], 2 per-row bias[m]
//   OUT_SPLIT: 0 -> fp32 Cf;  1 -> bf16 pair (Ch, Cl)
// ============================================================================
#define KDEPTH   1024
#define BKC      32
#define NCHUNK   (KDEPTH / BKC)     // 32
#define ROWB     64                 // bytes per smem row
#define TILE_B   8192               // 128 rows x 64 B
#define STAGE_B  (4 * TILE_B)       // Ah, Al, Bh, Bl = 32 KB
#define NSTAGE   3
#define GEMM_SMEM (1024 + NSTAGE * STAGE_B)   // ~97 KB -> 2 CTAs/SM

template<int BIAS_MODE, int OUT_SPLIT>
__global__ void __launch_bounds__(256, 2)
gemm_split(const __nv_bfloat16* __restrict__ Ah, const __nv_bfloat16* __restrict__ Al,
           int lda, size_t sA,
           const __nv_bfloat16* __restrict__ Bh, const __nv_bfloat16* __restrict__ Bl,
           int ldb, size_t sB,
           const float* __restrict__ bias,
           float* __restrict__ Cf, __nv_bfloat16* __restrict__ Ch,
           __nv_bfloat16* __restrict__ Cl,
           int ldc, size_t sC)
{
    extern __shared__ char smem[];
    const int tid  = threadIdx.x;
    const int wid  = tid >> 5;
    const int lane = tid & 31;
    const int wm   = wid >> 2;     // 0..1  (M)
    const int wn   = wid & 3;      // 0..3  (N)
    const int z    = blockIdx.z;

    Ah += (size_t)z * sA;  Al += (size_t)z * sA;
    Bh += (size_t)z * sB;  Bl += (size_t)z * sB;
    if (OUT_SPLIT) { Ch += (size_t)z * sC; Cl += (size_t)z * sC; }
    else           { Cf += (size_t)z * sC; }

    const int rowBase = blockIdx.y * 128;
    const int colBase = blockIdx.x * 128;

    const uint32_t raw  = smem_u32_of(smem);
    const uint32_t base = (raw + 1023u) & ~1023u;

    const __nv_bfloat16* aAh = Ah + (size_t)rowBase * lda;
    const __nv_bfloat16* aAl = Al + (size_t)rowBase * lda;
    const __nv_bfloat16* aBh = Bh + (size_t)colBase * ldb;
    const __nv_bfloat16* aBl = Bl + (size_t)colBase * ldb;

    auto load_chunk = [&](int k0, uint32_t stg) {
#pragma unroll
        for (int it = 0; it < 2; ++it) {
            const int slot = tid + it * 256;     // 0..511
            const int r    = slot >> 2;          // 0..127
            const int seg  = slot & 3;           // 16B segment
            const uint32_t so = sw64((uint32_t)(r * ROWB + seg * 16));
            const size_t ga = (size_t)r * lda + k0 + seg * 8;
            const size_t gb = (size_t)r * ldb + k0 + seg * 8;
            cp16(stg + 0 * TILE_B + so, aAh + ga);
            cp16(stg + 1 * TILE_B + so, aAl + ga);
            cp16(stg + 2 * TILE_B + so, aBh + gb);
            cp16(stg + 3 * TILE_B + so, aBl + gb);
        }
        CP_COMMIT();
    };

    float acc[4][4][4];
#pragma unroll
    for (int mt = 0; mt < 4; ++mt)
#pragma unroll
        for (int nt = 0; nt < 4; ++nt)
#pragma unroll
            for (int e = 0; e < 4; ++e) acc[mt][nt][e] = 0.f;

    load_chunk(0, base + 0 * STAGE_B);
    load_chunk(BKC, base + 1 * STAGE_B);

    const uint32_t aRow = (uint32_t)(wm * 64 + (lane & 15));
    const uint32_t aCb  = (uint32_t)((lane >> 4) << 4);
    const uint32_t bRow = (uint32_t)(wn * 32 + ((lane >> 4) << 3) + (lane & 7));
    const uint32_t bCb  = (uint32_t)(((lane >> 3) & 1) << 4);

#pragma unroll 1
    for (int i = 0; i < NCHUNK; ++i) {
        if (i + 1 < NCHUNK) { CP_WAIT(1); } else { CP_WAIT(0); }
        __syncthreads();

        if (i + 2 < NCHUNK)
            load_chunk((i + 2) * BKC, base + ((i + 2) % NSTAGE) * STAGE_B);

        const uint32_t stg = base + (i % NSTAGE) * STAGE_B;
        const uint32_t sAh = stg;
        const uint32_t sAl = stg + 1 * TILE_B;
        const uint32_t sBh = stg + 2 * TILE_B;
        const uint32_t sBl = stg + 3 * TILE_B;

#pragma unroll
        for (int kk = 0; kk < 2; ++kk) {          // 2 x k16 = 32
            uint32_t bh[4][2], bl[4][2];
#pragma unroll
            for (int j = 0; j < 2; ++j) {
                const uint32_t off = sw64((bRow + j * 16) * ROWB + kk * 32 + bCb);
                uint32_t t[4];
                ldsm4(t, sBh + off);
                bh[j*2][0] = t[0]; bh[j*2][1] = t[1];
                bh[j*2+1][0] = t[2]; bh[j*2+1][1] = t[3];
                ldsm4(t, sBl + off);
                bl[j*2][0] = t[0]; bl[j*2][1] = t[1];
                bl[j*2+1][0] = t[2]; bl[j*2+1][1] = t[3];
            }
#pragma unroll
            for (int mt = 0; mt < 4; ++mt) {
                const uint32_t offA = sw64((aRow + mt * 16) * ROWB + kk * 32 + aCb);
                uint32_t ah[4];
                ldsm4(ah, sAh + offA);
#pragma unroll
                for (int nt = 0; nt < 4; ++nt) mma_bf16(acc[mt][nt], ah, bh[nt]);
#pragma unroll
                for (int nt = 0; nt < 4; ++nt) mma_bf16(acc[mt][nt], ah, bl[nt]);
                uint32_t al[4];
                ldsm4(al, sAl + offA);
#pragma unroll
                for (int nt = 0; nt < 4; ++nt) mma_bf16(acc[mt][nt], al, bh[nt]);
            }
        }
    }

    // ---- Epilogue ----
    const int l4 = lane >> 2;
    const int l2 = (lane & 3) * 2;
#pragma unroll
    for (int mt = 0; mt < 4; ++mt) {
#pragma unroll
        for (int half = 0; half < 2; ++half) {
            const int r = rowBase + wm * 64 + mt * 16 + l4 + half * 8;
            float rbias = 0.f;
            if (BIAS_MODE == 2) rbias = __ldg(&bias[r]);
#pragma unroll
            for (int nt = 0; nt < 4; ++nt) {
                const int c = colBase + wn * 32 + nt * 8 + l2;
                float v0 = acc[mt][nt][half * 2 + 0];
                float v1 = acc[mt][nt][half * 2 + 1];
                if (BIAS_MODE == 1) {
                    float2 bv = *reinterpret_cast<const float2*>(&bias[c]);
                    v0 += bv.x; v1 += bv.y;
                } else if (BIAS_MODE == 2) {
                    v0 += rbias; v1 += rbias;
                }
                if (OUT_SPLIT == 0) {
                    float2 st; st.x = v0; st.y = v1;
                    *reinterpret_cast<float2*>(Cf + (size_t)r * ldc + c) = st;
                } else {
                    __nv_bfloat16 h0 = __float2bfloat16(v0);
                    __nv_bfloat16 h1 = __float2bfloat16(v1);
                    __nv_bfloat16 q0 = __float2bfloat16(v0 - __bfloat162float(h0));
                    __nv_bfloat16 q1 = __float2bfloat16(v1 - __bfloat162float(h1));
                    *reinterpret_cast<__nv_bfloat162*>(Ch + (size_t)r * ldc + c) =
                        __halves2bfloat162(h0, h1);
                    *reinterpret_cast<__nv_bfloat162*>(Cl + (size_t)r * ldc + c) =
                        __halves2bfloat162(q0, q1);
                }
            }
        }
    }
}

// ============================================================================
// Row softmax over 1024-wide rows; fp32 in, bf16 hi/lo split out.
// ============================================================================
__global__ void __launch_bounds__(256)
softmax_split(const float* __restrict__ S, __nv_bfloat16* __restrict__ Ph,
              __nv_bfloat16* __restrict__ Pl)
{
    const int row = blockIdx.x;
    const int t = threadIdx.x;
    const int w = t >> 5, l = t & 31;

    float4 v = *reinterpret_cast<const float4*>(S + (size_t)row * 1024 + t * 4);

    float m = fmaxf(fmaxf(v.x, v.y), fmaxf(v.z, v.w));
#pragma unroll
    for (int o = 16; o; o >>= 1) m = fmaxf(m, __shfl_xor_sync(0xffffffffu, m, o));

    __shared__ float redm[8], reds[8];
    if (l == 0) redm[w] = m;
    __syncthreads();
    float rm = fmaxf(fmaxf(fmaxf(redm[0], redm[1]), fmaxf(redm[2], redm[3])),
                     fmaxf(fmaxf(redm[4], redm[5]), fmaxf(redm[6], redm[7])));

    v.x = __expf(v.x - rm);
    v.y = __expf(v.y - rm);
    v.z = __expf(v.z - rm);
    v.w = __expf(v.w - rm);

    float s = v.x + v.y + v.z + v.w;
#pragma unroll
    for (int o = 16; o; o >>= 1) s += __shfl_xor_sync(0xffffffffu, s, o);
    if (l == 0) reds[w] = s;
    __syncthreads();
    float tot = (reds[0] + reds[1]) + (reds[2] + reds[3])
              + (reds[4] + reds[5]) + (reds[6] + reds[7]);

    const float inv = 1.0f / tot;
    float w0 = v.x * inv, w1 = v.y * inv, w2 = v.z * inv, w3 = v.w * inv;

    __nv_bfloat16 h0 = __float2bfloat16(w0), h1 = __float2bfloat16(w1);
    __nv_bfloat16 h2 = __float2bfloat16(w2), h3 = __float2bfloat16(w3);
    __nv_bfloat16 l0 = __float2bfloat16(w0 - __bfloat162float(h0));
    __nv_bfloat16 l1 = __float2bfloat16(w1 - __bfloat162float(h1));
    __nv_bfloat16 l2 = __float2bfloat16(w2 - __bfloat162float(h2));
    __nv_bfloat16 l3 = __float2bfloat16(w3 - __bfloat162float(h3));

    const size_t p2 = ((size_t)row * 1024 + t * 4) >> 1;
    reinterpret_cast<__nv_bfloat162*>(Ph)[p2 + 0] = __halves2bfloat162(h0, h1);
    reinterpret_cast<__nv_bfloat162*>(Ph)[p2 + 1] = __halves2bfloat162(h2, h3);
    reinterpret_cast<__nv_bfloat162*>(Pl)[p2 + 0] = __halves2bfloat162(l0, l1);
    reinterpret_cast<__nv_bfloat162*>(Pl)[p2 + 1] = __halves2bfloat162(l2, l3);
}

// ============================================================================
// kernel_launch — 3-way stream parallelism over the Q/K/V dependency graph:
//   main: Wq,meme -> Q-proj -> [wait K] scores -> softmax -> [wait V] PV
//   s1:   Wk,text -> K-proj
//   s2:   Wv,emoji -> VT-proj   (overlaps scores+softmax entirely)
// ============================================================================
extern "C" void kernel_launch(void* const* d_in, const int* in_sizes, int n_in,
                              void* d_out, int out_size)
{
    const float* meme  = (const float*)d_in[0];
    const float* text  = (const float*)d_in[1];
    const float* emoji = (const float*)d_in[2];
    const float* Wq    = (const float*)d_in[3];
    const float* bq    = (const float*)d_in[4];
    const float* Wk    = (const float*)d_in[5];
    const float* bk    = (const float*)d_in[6];
    const float* Wv    = (const float*)d_in[7];
    const float* bv    = (const float*)d_in[8];
    float* out = (float*)d_out;

    __nv_bfloat16 *Xmh,*Xml,*Xth,*Xtl,*Xeh,*Xel,*Wqh,*Wql,*Wkh,*Wkl,*Wvh,*Wvl;
    __nv_bfloat16 *Qh,*Ql,*Kh,*Kl,*VTh,*VTl,*Ph,*Pl;
    float* S;
    cudaGetSymbolAddress((void**)&Xmh, g_Xmh); cudaGetSymbolAddress((void**)&Xml, g_Xml);
    cudaGetSymbolAddress((void**)&Xth, g_Xth); cudaGetSymbolAddress((void**)&Xtl, g_Xtl);
    cudaGetSymbolAddress((void**)&Xeh, g_Xeh); cudaGetSymbolAddress((void**)&Xel, g_Xel);
    cudaGetSymbolAddress((void**)&Wqh, g_Wqh); cudaGetSymbolAddress((void**)&Wql, g_Wql);
    cudaGetSymbolAddress((void**)&Wkh, g_Wkh); cudaGetSymbolAddress((void**)&Wkl, g_Wkl);
    cudaGetSymbolAddress((void**)&Wvh, g_Wvh); cudaGetSymbolAddress((void**)&Wvl, g_Wvl);
    cudaGetSymbolAddress((void**)&Qh, g_Qh);   cudaGetSymbolAddress((void**)&Ql, g_Ql);
    cudaGetSymbolAddress((void**)&Kh, g_Kh);   cudaGetSymbolAddress((void**)&Kl, g_Kl);
    cudaGetSymbolAddress((void**)&VTh, g_VTh); cudaGetSymbolAddress((void**)&VTl, g_VTl);
    cudaGetSymbolAddress((void**)&Ph, g_Ph);   cudaGetSymbolAddress((void**)&Pl, g_Pl);
    cudaGetSymbolAddress((void**)&S, g_S);

    static bool inited = false;
    static cudaStream_t s1, s2;
    static cudaEvent_t evFork, evK, evV;
    if (!inited) {
        cudaStreamCreateWithFlags(&s1, cudaStreamNonBlocking);
        cudaStreamCreateWithFlags(&s2, cudaStreamNonBlocking);
        cudaEventCreateWithFlags(&evFork, cudaEventDisableTiming);
        cudaEventCreateWithFlags(&evK, cudaEventDisableTiming);
        cudaEventCreateWithFlags(&evV, cudaEventDisableTiming);
        cudaFuncSetAttribute(gemm_split<1, 1>, cudaFuncAttributeMaxDynamicSharedMemorySize, GEMM_SMEM);
        cudaFuncSetAttribute(gemm_split<2, 1>, cudaFuncAttributeMaxDynamicSharedMemorySize, GEMM_SMEM);
        cudaFuncSetAttribute(gemm_split<0, 0>, cudaFuncAttributeMaxDynamicSharedMemorySize, GEMM_SMEM);
        inited = true;
    }

    const size_t bstr = (size_t)SEQ * HID;          // 1M elems per batch
    const int nx4 = (MTOT * HID) / 4;
    const int nw4 = (HID * HID) / 4;
    const int gX = (nx4 + 1023) / 1024;             // split grid (4 f4/thread)
    const int gW = (nw4 + 1023) / 1024;

    dim3 blk(256);
    dim3 gProj(HID / 128, MTOT / 128, 1);           // (8, 128)
    dim3 gVT(MTOT / 128, HID / 128, 1);             // (128, 8)
    dim3 gAtt(SEQ / 128, SEQ / 128, NBAT);          // (8, 8, 16)

    // Fork side streams from the capture-origin stream.
    cudaEventRecord(evFork, 0);
    cudaStreamWaitEvent(s1, evFork, 0);
    cudaStreamWaitEvent(s2, evFork, 0);

    // s1: K path
    f32_to_split<<<gW, blk, 0, s1>>>(Wk, Wkh, Wkl, nw4);
    f32_to_split<<<gX, blk, 0, s1>>>(text, Xth, Xtl, nx4);
    gemm_split<1, 1><<<gProj, blk, GEMM_SMEM, s1>>>(Xth, Xtl, HID, 0, Wkh, Wkl, HID, 0,
                                                    bk, nullptr, Kh, Kl, HID, 0);
    cudaEventRecord(evK, s1);

    // s2: V path (VT[a][lg] = Wv[a][:] . emoji[lg][:] + bv[a], ldc=16384)
    f32_to_split<<<gW, blk, 0, s2>>>(Wv, Wvh, Wvl, nw4);
    f32_to_split<<<gX, blk, 0, s2>>>(emoji, Xeh, Xel, nx4);
    gemm_split<2, 1><<<gVT, blk, GEMM_SMEM, s2>>>(Wvh, Wvl, HID, 0, Xeh, Xel, HID, 0,
                                                  bv, nullptr, VTh, VTl, MTOT, 0);
    cudaEventRecord(evV, s2);

    // main: Q path
    f32_to_split<<<gW, blk>>>(Wq, Wqh, Wql, nw4);
    f32_to_split<<<gX, blk>>>(meme, Xmh, Xml, nx4);
    gemm_split<1, 1><<<gProj, blk, GEMM_SMEM>>>(Xmh, Xml, HID, 0, Wqh, Wql, HID, 0,
                                                bq, nullptr, Qh, Ql, HID, 0);

    // Need K before scores (VT may still be running — overlaps scores+softmax).
    cudaStreamWaitEvent(0, evK, 0);
    gemm_split<0, 0><<<gAtt, blk, GEMM_SMEM>>>(Qh, Ql, HID, bstr, Kh, Kl, HID, bstr,
                                               nullptr, S, nullptr, nullptr, SEQ, bstr);
    softmax_split<<<MTOT, blk>>>(S, Ph, Pl);

    // Need VT before PV.
    cudaStreamWaitEvent(0, evV, 0);
    gemm_split<0, 0><<<gAtt, blk, GEMM_SMEM>>>(Ph, Pl, SEQ, bstr,
                                               VTh, VTl, MTOT, (size_t)SEQ,
                                               nullptr, out, nullptr, nullptr, HID, bstr);
}